// round 16
// baseline (speedup 1.0000x reference)
#include <cuda_runtime.h>
#include <cuda_bf16.h>
#include <cuda_fp16.h>
#include <math.h>

#define NATOMS 32768
#define MNBR   12
#define ORIG   92
#define NBRF   41
#define KPAD   48
#define AF     64
#define TWOAF  128
#define KTOT   (2*AF + NBRF)   // 169
#define EDGES  (NATOMS*MNBR)   // 393216
#define NT48   (EDGES/48)      // 8192
#define NCONV  3
#define ATOMS_PER 32
#define NCRYS  (NATOMS/ATOMS_PER)
#define HF     128
#define BNEPS  1e-5f

// ---------------- scratch ----------------
__device__ float  d_x[NATOMS*AF];
__device__ __half d_Psh[(size_t)NATOMS*TWOAF];   // x@W_self + b (fp16)
__device__ __half d_Pnh[(size_t)NATOMS*TWOAF];   // x@W_nbr (fp16)
__device__ __half d_gh[(size_t)EDGES*TWOAF];     // edge pre-activations (100 MB, L2-mostly)
__device__ uint4  d_Ah[(size_t)(EDGES/16)*3*32]; // nbr_fea A-fragments (37.7 MB)
__device__ uint4  d_Axh[(NATOMS/16)*4*32];       // x A-fragments (4 MB)
__device__ __half d_Weh[KPAD*TWOAF];             // W_edge fp16 (K padded 48)
__device__ uint2  d_Wph[32*4*32];                // [Wself|Wnbr] B-fragments
__device__ float  d_summed[NATOMS*AF];
__device__ float  d_s1[TWOAF], d_q1[TWOAF];
__device__ float  d_s2[AF], d_q2[AF];

__device__ __forceinline__ float softplusf(float x) {
    return fmaxf(x, 0.0f) + __logf(1.0f + __expf(-fabsf(x)));
}
__device__ __forceinline__ float sigmoidf(float x) {
    return __fdividef(1.0f, 1.0f + __expf(-x));
}

// ---------------- embedding ----------------
__global__ __launch_bounds__(256) void k_embed(
    const float* __restrict__ atom_fea,
    const float* __restrict__ W,
    const float* __restrict__ b)
{
    __shared__ float W_sh[ORIG*AF];
    __shared__ float a_sh[4][ORIG];
    int tid = threadIdx.x;
    for (int i = tid; i < ORIG*AF; i += 256) W_sh[i] = W[i];
    int r0 = blockIdx.x * 4;
    for (int i = tid; i < 4*ORIG; i += 256) {
        int r = i / ORIG, k = i % ORIG;
        a_sh[r][k] = atom_fea[(r0 + r)*ORIG + k];
    }
    __syncthreads();
    int rl = tid >> 6;
    int c  = tid & 63;
    float acc = b[c];
    #pragma unroll 4
    for (int k = 0; k < ORIG; k++) acc += a_sh[rl][k] * W_sh[k*AF + c];
    d_x[(r0 + rl)*AF + c] = acc;
}

// ---------------- one-time: nbr_fea -> A-fragment fp16 buffer ----------------
__global__ __launch_bounds__(256) void k_cvt_nbr(const float* __restrict__ nbr_fea)
{
    int idx  = blockIdx.x*256 + threadIdx.x;   // < (E/16)*3*32
    int lane = idx & 31;
    int ks   = (idx >> 5) % 3;
    int t    = idx / 96;
    int r0 = t*16 + (lane >> 2);
    int c0 = ks*16 + (lane & 3)*2;

    float v[8];
    #pragma unroll
    for (int j = 0; j < 8; j++) {
        int r = r0 + ((j >> 1) & 1) * 8;
        int c = c0 + (j & 1) + (j >> 2) * 8;
        v[j] = (c < NBRF) ? nbr_fea[(size_t)r*NBRF + c] : 0.f;
    }
    __half2 h0 = __floats2half2_rn(v[0], v[1]);
    __half2 h1 = __floats2half2_rn(v[2], v[3]);
    __half2 h2 = __floats2half2_rn(v[4], v[5]);
    __half2 h3 = __floats2half2_rn(v[6], v[7]);
    uint4 st;
    st.x = *(unsigned*)&h0; st.y = *(unsigned*)&h1;
    st.z = *(unsigned*)&h2; st.w = *(unsigned*)&h3;
    d_Ah[idx] = st;
}

// ---------------- layer-0: x -> A-fragment buffer ----------------
__global__ __launch_bounds__(256) void k_cvt_x()
{
    int idx  = blockIdx.x*256 + threadIdx.x;   // < (NATOMS/16)*4*32
    int lane = idx & 31;
    int ks   = (idx >> 5) & 3;
    int t    = idx >> 7;
    int r0 = t*16 + (lane >> 2);
    int c0 = ks*16 + (lane & 3)*2;

    float v[8];
    #pragma unroll
    for (int j = 0; j < 8; j++) {
        int r = r0 + ((j >> 1) & 1) * 8;
        int c = c0 + (j & 1) + (j >> 2) * 8;
        v[j] = d_x[r*AF + c];
    }
    __half2 h0 = __floats2half2_rn(v[0], v[1]);
    __half2 h1 = __floats2half2_rn(v[2], v[3]);
    __half2 h2 = __floats2half2_rn(v[4], v[5]);
    __half2 h3 = __floats2half2_rn(v[6], v[7]);
    uint4 st;
    st.x = *(unsigned*)&h0; st.y = *(unsigned*)&h1;
    st.z = *(unsigned*)&h2; st.w = *(unsigned*)&h3;
    d_Axh[idx] = st;
}

// ---------------- per-layer prep: zero stats + W converts (fused) ----------------
__global__ __launch_bounds__(256) void k_prep(const float* __restrict__ Wc)
{
    int idx = blockIdx.x*256 + threadIdx.x;   // grid covers 6144 + 4096
    if (idx < TWOAF) { d_s1[idx] = 0.f; d_q1[idx] = 0.f; }
    if (idx < AF)    { d_s2[idx] = 0.f; d_q2[idx] = 0.f; }

    if (idx < KPAD*TWOAF) {
        int k = idx >> 7, n = idx & 127;
        d_Weh[idx] = __float2half((k < NBRF) ? Wc[(size_t)(TWOAF + k)*TWOAF + n] : 0.f);
    } else {
        int widx = idx - KPAD*TWOAF;
        if (widx < 4096) {
            int lane = widx & 31;
            int ks   = (widx >> 5) & 3;
            int nt   = widx >> 7;
            int n  = nt*8 + (lane >> 2);
            int k0 = ks*16 + (lane & 3)*2;
            float w00, w01, w10, w11;
            if (n < TWOAF) {
                w00 = Wc[(k0    )*TWOAF + n]; w01 = Wc[(k0 + 1)*TWOAF + n];
                w10 = Wc[(k0 + 8)*TWOAF + n]; w11 = Wc[(k0 + 9)*TWOAF + n];
            } else {
                int nn = n - TWOAF;
                w00 = Wc[(AF + k0    )*TWOAF + nn]; w01 = Wc[(AF + k0 + 1)*TWOAF + nn];
                w10 = Wc[(AF + k0 + 8)*TWOAF + nn]; w11 = Wc[(AF + k0 + 9)*TWOAF + nn];
            }
            __half2 b0 = __floats2half2_rn(w00, w01);
            __half2 b1 = __floats2half2_rn(w10, w11);
            uint2 st;
            st.x = *(unsigned*)&b0; st.y = *(unsigned*)&b1;
            d_Wph[widx] = st;
        }
    }
}

// ---------------- atom GEMM via HMMA: P_self / P_nbr ----------------
__global__ __launch_bounds__(256) void k_atom_mma(const float* __restrict__ bc)
{
    int tid  = threadIdx.x;
    int warp = tid >> 5;
    int lane = tid & 31;
    int atile = blockIdx.x;

    float acc[4][4];
    #pragma unroll
    for (int nt = 0; nt < 4; nt++)
        #pragma unroll
        for (int j = 0; j < 4; j++) acc[nt][j] = 0.f;

    #pragma unroll
    for (int ks = 0; ks < 4; ks++) {
        uint4 a = d_Axh[(atile*4 + ks)*32 + lane];
        #pragma unroll
        for (int nt = 0; nt < 4; nt++) {
            uint2 b = d_Wph[((warp*4 + nt)*4 + ks)*32 + lane];
            asm volatile(
                "mma.sync.aligned.m16n8k16.row.col.f32.f16.f16.f32 "
                "{%0,%1,%2,%3}, {%4,%5,%6,%7}, {%8,%9}, {%0,%1,%2,%3};\n"
                : "+f"(acc[nt][0]), "+f"(acc[nt][1]), "+f"(acc[nt][2]), "+f"(acc[nt][3])
                : "r"(a.x), "r"(a.y), "r"(a.z), "r"(a.w), "r"(b.x), "r"(b.y));
        }
    }

    int r  = lane >> 2;
    int a0 = atile * 16;
    bool self = (warp < 4);
    __half* dst = self ? d_Psh : d_Pnh;
    #pragma unroll
    for (int nt = 0; nt < 4; nt++) {
        int c = warp*32 + nt*8 + (lane & 3)*2;
        float b0 = 0.f, b1 = 0.f;
        if (self) { b0 = bc[c]; b1 = bc[c + 1]; }
        int cc = self ? c : c - TWOAF;
        __half2 h0 = __floats2half2_rn(acc[nt][0] + b0, acc[nt][1] + b1);
        __half2 h1 = __floats2half2_rn(acc[nt][2] + b0, acc[nt][3] + b1);
        *(__half2*)&dst[(size_t)(a0 + r    )*TWOAF + cc] = h0;
        *(__half2*)&dst[(size_t)(a0 + r + 8)*TWOAF + cc] = h1;
    }
}

// ---------------- edge kernel: 48-edge (4-atom) tiles, Ps smem-staged, g store + BN1 stats ----------------
// warp w covers cols w*16..+15; epilogue: eg=tid&15 -> edges eg*3..+2 (all in atom eg>>2), cg=tid>>4
__global__ __launch_bounds__(256, 3) void k_edge_mma(
    const int* __restrict__ nbr_idx)
{
    __shared__ __half C_sh[48*136];      // 13056 B
    __shared__ __half Ps_sh[4*TWOAF];    // 1024 B
    __shared__ int nb_sh[48];

    int tid  = threadIdx.x;
    int warp = tid >> 5;
    int lane = tid & 31;
    int eg   = tid & 15;
    int cg   = tid >> 4;

    unsigned bfrag[2][3][2];
    {
        int nb_ = warp*16 + (lane >> 2);
        #pragma unroll
        for (int nt = 0; nt < 2; nt++) {
            int n = nb_ + nt*8;
            #pragma unroll
            for (int ks = 0; ks < 3; ks++) {
                int k0 = ks*16 + (lane & 3)*2;
                __half2 b0 = __halves2half2(d_Weh[k0*TWOAF + n],     d_Weh[(k0+1)*TWOAF + n]);
                __half2 b1 = __halves2half2(d_Weh[(k0+8)*TWOAF + n], d_Weh[(k0+9)*TWOAF + n]);
                bfrag[nt][ks][0] = *(unsigned*)&b0;
                bfrag[nt][ks][1] = *(unsigned*)&b1;
            }
        }
    }

    float s8[8], q8[8];
    #pragma unroll
    for (int j = 0; j < 8; j++) { s8[j] = 0.f; q8[j] = 0.f; }

    int r    = lane >> 2;
    int ncol = warp*16 + (lane & 3)*2;

    for (int tile = blockIdx.x; tile < NT48; tile += gridDim.x) {
        __syncthreads();
        if (tid < 12) *(int4*)&nb_sh[tid*4] = *(const int4*)&nbr_idx[tile*48 + tid*4];
        if (tid < 64) {
            int a_loc = tid >> 4, t16 = tid & 15;
            *(uint4*)&Ps_sh[a_loc*TWOAF + t16*8] =
                *(const uint4*)&d_Psh[(size_t)(tile*4 + a_loc)*TWOAF + t16*8];
        }

        float acc[3][2][4];
        #pragma unroll
        for (int mt = 0; mt < 3; mt++)
            #pragma unroll
            for (int nt = 0; nt < 2; nt++)
                #pragma unroll
                for (int j = 0; j < 4; j++) acc[mt][nt][j] = 0.f;

        #pragma unroll
        for (int ks = 0; ks < 3; ks++) {
            #pragma unroll
            for (int mt = 0; mt < 3; mt++) {
                uint4 a = d_Ah[(size_t)((tile*3 + mt)*3 + ks)*32 + lane];
                #pragma unroll
                for (int nt = 0; nt < 2; nt++) {
                    asm volatile(
                        "mma.sync.aligned.m16n8k16.row.col.f32.f16.f16.f32 "
                        "{%0,%1,%2,%3}, {%4,%5,%6,%7}, {%8,%9}, {%0,%1,%2,%3};\n"
                        : "+f"(acc[mt][nt][0]), "+f"(acc[mt][nt][1]),
                          "+f"(acc[mt][nt][2]), "+f"(acc[mt][nt][3])
                        : "r"(a.x), "r"(a.y), "r"(a.z), "r"(a.w),
                          "r"(bfrag[nt][ks][0]), "r"(bfrag[nt][ks][1]));
                }
            }
        }

        #pragma unroll
        for (int mt = 0; mt < 3; mt++)
            #pragma unroll
            for (int nt = 0; nt < 2; nt++) {
                __half2 h01 = __floats2half2_rn(acc[mt][nt][0], acc[mt][nt][1]);
                __half2 h23 = __floats2half2_rn(acc[mt][nt][2], acc[mt][nt][3]);
                *(__half2*)&C_sh[(mt*16 + r)*136 + ncol + nt*8]     = h01;
                *(__half2*)&C_sh[(mt*16 + r + 8)*136 + ncol + nt*8] = h23;
            }
        __syncthreads();

        int a_loc = eg >> 2;
        #pragma unroll
        for (int i = 0; i < 3; i++) {
            int el = eg*3 + i;
            int e  = tile*48 + el;
            int nb = nb_sh[el];
            uint4 cvv = *(const uint4*)&C_sh[el*136 + cg*8];
            uint4 psv = *(const uint4*)&Ps_sh[a_loc*TWOAF + cg*8];
            uint4 pnv = *reinterpret_cast<const uint4*>(&d_Pnh[(size_t)nb*TWOAF + cg*8]);
            const __half2* ch = (const __half2*)&cvv;
            const __half2* ph = (const __half2*)&psv;
            const __half2* nh = (const __half2*)&pnv;
            float g[8];
            #pragma unroll
            for (int p = 0; p < 4; p++) {
                float2 cf = __half22float2(ch[p]);
                float2 pf = __half22float2(ph[p]);
                float2 nf = __half22float2(nh[p]);
                g[2*p]   = cf.x + pf.x + nf.x;
                g[2*p+1] = cf.y + pf.y + nf.y;
            }
            #pragma unroll
            for (int j = 0; j < 8; j++) { s8[j] += g[j]; q8[j] += g[j]*g[j]; }
            __half2 h[4];
            #pragma unroll
            for (int p = 0; p < 4; p++) h[p] = __floats2half2_rn(g[2*p], g[2*p+1]);
            uint4 st;
            st.x = *(unsigned*)&h[0]; st.y = *(unsigned*)&h[1];
            st.z = *(unsigned*)&h[2]; st.w = *(unsigned*)&h[3];
            *reinterpret_cast<uint4*>(&d_gh[(size_t)e*TWOAF + cg*8]) = st;
        }
    }

    #pragma unroll
    for (int m = 1; m < 16; m <<= 1) {
        #pragma unroll
        for (int j = 0; j < 8; j++) {
            s8[j] += __shfl_xor_sync(0xffffffffu, s8[j], m);
            q8[j] += __shfl_xor_sync(0xffffffffu, q8[j], m);
        }
    }
    if (eg == 0) {
        #pragma unroll
        for (int j = 0; j < 8; j++) {
            atomicAdd(&d_s1[cg*8 + j], s8[j]);
            atomicAdd(&d_q1[cg*8 + j], q8[j]);
        }
    }
}

// ---------------- gate + sum (fp16 input), BN1 finalize inlined, BN2 stats ----------------
// block = 32 atoms x 8 threads; thread covers 8 cols
__global__ __launch_bounds__(256) void k_gate_sum(
    const float* __restrict__ g1, const float* __restrict__ b1)
{
    __shared__ float sc1[TWOAF], sh1[TWOAF];
    __shared__ float s2_sh[AF], q2_sh[AF];
    int tid = threadIdx.x;
    if (tid < TWOAF) {
        float inv_n = 1.0f / (float)EDGES;
        float mu  = d_s1[tid] * inv_n;
        float var = d_q1[tid] * inv_n - mu*mu;
        float sc  = rsqrtf(var + BNEPS) * g1[tid];
        sc1[tid] = sc;
        sh1[tid] = b1[tid] - mu * sc;
    }
    if (tid < AF) { s2_sh[tid] = 0.f; q2_sh[tid] = 0.f; }
    __syncthreads();

    int al = tid >> 3;
    int c0 = (tid & 7) * 8;
    int a  = blockIdx.x*32 + al;

    float scf[8], shf[8], scs[8], shs[8];
    #pragma unroll
    for (int j = 0; j < 8; j++) {
        scf[j] = sc1[c0 + j];      shf[j] = sh1[c0 + j];
        scs[j] = sc1[AF + c0 + j]; shs[j] = sh1[AF + c0 + j];
    }

    float accv[8];
    #pragma unroll
    for (int j = 0; j < 8; j++) accv[j] = 0.f;

    size_t base = (size_t)a * MNBR * TWOAF;
    #pragma unroll
    for (int m = 0; m < MNBR; m++) {
        uint4 fv = *reinterpret_cast<const uint4*>(&d_gh[base + m*TWOAF + c0]);
        uint4 sv = *reinterpret_cast<const uint4*>(&d_gh[base + m*TWOAF + AF + c0]);
        const __half2* fh = (const __half2*)&fv;
        const __half2* sh = (const __half2*)&sv;
        #pragma unroll
        for (int p = 0; p < 4; p++) {
            float2 f = __half22float2(fh[p]);
            float2 s = __half22float2(sh[p]);
            float fx = f.x*scf[2*p]   + shf[2*p];
            float fy = f.y*scf[2*p+1] + shf[2*p+1];
            float sx = s.x*scs[2*p]   + shs[2*p];
            float sy = s.y*scs[2*p+1] + shs[2*p+1];
            accv[2*p]   += sigmoidf(fx) * softplusf(sx);
            accv[2*p+1] += sigmoidf(fy) * softplusf(sy);
        }
    }
    *(float4*)&d_summed[a*AF + c0]     = *(float4*)&accv[0];
    *(float4*)&d_summed[a*AF + c0 + 4] = *(float4*)&accv[4];
    #pragma unroll
    for (int j = 0; j < 8; j++) {
        atomicAdd(&s2_sh[c0 + j], accv[j]);
        atomicAdd(&q2_sh[c0 + j], accv[j]*accv[j]);
    }
    __syncthreads();
    if (tid < AF) {
        atomicAdd(&d_s2[tid], s2_sh[tid]);
        atomicAdd(&d_q2[tid], q2_sh[tid]);
    }
}

// ---------------- fused: BN2 finalize + x update + A-fragment emission ----------------
// block = 16 atoms (grid 2048)
__global__ __launch_bounds__(256) void k_update_cvt(
    const float* __restrict__ g2, const float* __restrict__ b2)
{
    __shared__ float x_sh[16*64];
    __shared__ float sc2[AF], sh2[AF];
    int tid  = threadIdx.x;
    if (tid < AF) {
        float inv_n = 1.0f / (float)NATOMS;
        float mu  = d_s2[tid] * inv_n;
        float var = d_q2[tid] * inv_n - mu*mu;
        float sc  = rsqrtf(var + BNEPS) * g2[tid];
        sc2[tid] = sc;
        sh2[tid] = b2[tid] - mu * sc;
    }
    __syncthreads();

    int base = blockIdx.x*1024 + tid*4;
    int c    = (tid*4) & 63;

    float4 sm = *(const float4*)&d_summed[base];
    float4 xv = *(const float4*)&d_x[base];
    float4 nx;
    nx.x = softplusf(xv.x + sm.x*sc2[c]   + sh2[c]);
    nx.y = softplusf(xv.y + sm.y*sc2[c+1] + sh2[c+1]);
    nx.z = softplusf(xv.z + sm.z*sc2[c+2] + sh2[c+2]);
    nx.w = softplusf(xv.w + sm.w*sc2[c+3] + sh2[c+3]);
    *(float4*)&d_x[base]   = nx;
    *(float4*)&x_sh[tid*4] = nx;
    __syncthreads();

    if (tid < 128) {
        int ks = tid >> 5, lane = tid & 31;
        int r0 = lane >> 2;
        int c0 = ks*16 + (lane & 3)*2;
        float v[8];
        #pragma unroll
        for (int j = 0; j < 8; j++) {
            int r  = r0 + ((j >> 1) & 1) * 8;
            int cc = c0 + (j & 1) + (j >> 2) * 8;
            v[j] = x_sh[r*64 + cc];
        }
        __half2 h0 = __floats2half2_rn(v[0], v[1]);
        __half2 h1 = __floats2half2_rn(v[2], v[3]);
        __half2 h2 = __floats2half2_rn(v[4], v[5]);
        __half2 h3 = __floats2half2_rn(v[6], v[7]);
        uint4 st;
        st.x = *(unsigned*)&h0; st.y = *(unsigned*)&h1;
        st.z = *(unsigned*)&h2; st.w = *(unsigned*)&h3;
        d_Axh[(blockIdx.x*4 + ks)*32 + lane] = st;
    }
}

// ---------------- pool + head MLP ----------------
__global__ __launch_bounds__(128) void k_head(
    const float* __restrict__ fc1W, const float* __restrict__ fc1b,
    const float* __restrict__ fc2W, const float* __restrict__ fc2b,
    const float* __restrict__ outW, const float* __restrict__ outb,
    float* __restrict__ out)
{
    __shared__ float p[AF];
    __shared__ float h1[HF];
    __shared__ float red[HF];
    int tid = threadIdx.x;
    int b = blockIdx.x;

    if (tid < AF) {
        const float* xb = &d_x[(size_t)b * ATOMS_PER * AF];
        float s = 0.f;
        #pragma unroll
        for (int a = 0; a < ATOMS_PER; a++) s += xb[a*AF + tid];
        p[tid] = softplusf(s * (1.0f/ATOMS_PER));
    }
    __syncthreads();

    float acc = fc1b[tid];
    #pragma unroll 4
    for (int k = 0; k < AF; k++) acc += p[k] * fc1W[k*HF + tid];
    h1[tid] = softplusf(acc);
    __syncthreads();

    float acc2 = fc2b[tid];
    #pragma unroll 4
    for (int k = 0; k < HF; k++) acc2 += h1[k] * fc2W[k*HF + tid];
    float h2 = softplusf(acc2);

    red[tid] = h2 * outW[tid];
    __syncthreads();
    for (int s = HF/2; s > 0; s >>= 1) {
        if (tid < s) red[tid] += red[tid + s];
        __syncthreads();
    }
    if (tid == 0) out[b] = red[0] + outb[0];
}

// ---------------- launch ----------------
extern "C" void kernel_launch(void* const* d_in, const int* in_sizes, int n_in,
                              void* d_out, int out_size)
{
    const float* atom_fea = (const float*)d_in[0];
    const float* nbr_fea  = (const float*)d_in[1];
    const int*   nbr_idx  = (const int*)  d_in[2];
    const float* embW  = (const float*)d_in[4];
    const float* embB  = (const float*)d_in[5];
    const float* convW = (const float*)d_in[6];
    const float* convB = (const float*)d_in[7];
    const float* bn1g  = (const float*)d_in[8];
    const float* bn1b  = (const float*)d_in[9];
    const float* bn2g  = (const float*)d_in[10];
    const float* bn2b  = (const float*)d_in[11];
    const float* fc1W  = (const float*)d_in[12];
    const float* fc1b  = (const float*)d_in[13];
    const float* fc2W  = (const float*)d_in[14];
    const float* fc2b  = (const float*)d_in[15];
    const float* outW  = (const float*)d_in[16];
    const float* outb  = (const float*)d_in[17];
    float* out = (float*)d_out;

    k_embed<<<NATOMS/4, 256>>>(atom_fea, embW, embB);
    k_cvt_nbr<<<(EDGES/16)*3*32/256, 256>>>(nbr_fea);   // once: layer-invariant
    k_cvt_x<<<(NATOMS/16)*4*32/256, 256>>>();           // layer-0 fragments

    for (int l = 0; l < NCONV; l++) {
        const float* Wl = convW + (size_t)l*KTOT*TWOAF;
        k_prep<<<(KPAD*TWOAF + 4096 + 255)/256, 256>>>(Wl);
        k_atom_mma<<<NATOMS/16, 256>>>(convB + l*TWOAF);
        k_edge_mma<<<444, 256>>>(nbr_idx);
        k_gate_sum<<<NATOMS/32, 256>>>(bn1g + l*TWOAF, bn1b + l*TWOAF);
        k_update_cvt<<<NATOMS*AF/1024, 256>>>(bn2g + l*AF, bn2b + l*AF);
    }

    k_head<<<NCRYS, 128>>>(fc1W, fc1b, fc2W, fc2b, outW, outb, out);
}

// round 17
// speedup vs baseline: 1.0361x; 1.0361x over previous
#include <cuda_runtime.h>
#include <cuda_bf16.h>
#include <cuda_fp16.h>
#include <math.h>

#define NATOMS 32768
#define MNBR   12
#define ORIG   92
#define NBRF   41
#define KPAD   48
#define AF     64
#define TWOAF  128
#define KTOT   (2*AF + NBRF)   // 169
#define EDGES  (NATOMS*MNBR)   // 393216
#define NT64   (EDGES/64)      // 6144
#define NCONV  3
#define ATOMS_PER 32
#define NCRYS  (NATOMS/ATOMS_PER)
#define HF     128
#define BNEPS  1e-5f

// ---------------- scratch ----------------
__device__ float  d_x[NATOMS*AF];
__device__ __half d_Psh[(size_t)NATOMS*TWOAF];   // x@W_self + b (fp16)
__device__ __half d_Pnh[(size_t)NATOMS*TWOAF];   // x@W_nbr (fp16)
__device__ __half d_gh[(size_t)EDGES*TWOAF];     // edge pre-activations (100 MB, L2-mostly)
__device__ uint4  d_Ah[(size_t)(EDGES/16)*3*32]; // nbr_fea A-fragments (37.7 MB)
__device__ uint4  d_Axh[(NATOMS/16)*4*32];       // x A-fragments (4 MB)
__device__ __half d_Weh[KPAD*TWOAF];             // W_edge fp16 (K padded 48)
__device__ uint2  d_Wph[32*4*32];                // [Wself|Wnbr] B-fragments
__device__ float  d_summed[NATOMS*AF];
__device__ float  d_s1[TWOAF], d_q1[TWOAF];
__device__ float  d_s2[AF], d_q2[AF];

__device__ __forceinline__ float softplusf(float x) {
    return fmaxf(x, 0.0f) + __logf(1.0f + __expf(-fabsf(x)));
}
__device__ __forceinline__ float sigmoidf(float x) {
    return __fdividef(1.0f, 1.0f + __expf(-x));
}

// ---------------- embedding ----------------
__global__ __launch_bounds__(256) void k_embed(
    const float* __restrict__ atom_fea,
    const float* __restrict__ W,
    const float* __restrict__ b)
{
    __shared__ float W_sh[ORIG*AF];
    __shared__ float a_sh[4][ORIG];
    int tid = threadIdx.x;
    for (int i = tid; i < ORIG*AF; i += 256) W_sh[i] = W[i];
    int r0 = blockIdx.x * 4;
    for (int i = tid; i < 4*ORIG; i += 256) {
        int r = i / ORIG, k = i % ORIG;
        a_sh[r][k] = atom_fea[(r0 + r)*ORIG + k];
    }
    __syncthreads();
    int rl = tid >> 6;
    int c  = tid & 63;
    float acc = b[c];
    #pragma unroll 4
    for (int k = 0; k < ORIG; k++) acc += a_sh[rl][k] * W_sh[k*AF + c];
    d_x[(r0 + rl)*AF + c] = acc;
}

// ---------------- one-time: nbr_fea -> A-fragment fp16 buffer ----------------
__global__ __launch_bounds__(256) void k_cvt_nbr(const float* __restrict__ nbr_fea)
{
    int idx  = blockIdx.x*256 + threadIdx.x;   // < (E/16)*3*32
    int lane = idx & 31;
    int ks   = (idx >> 5) % 3;
    int t    = idx / 96;
    int r0 = t*16 + (lane >> 2);
    int c0 = ks*16 + (lane & 3)*2;

    float v[8];
    #pragma unroll
    for (int j = 0; j < 8; j++) {
        int r = r0 + ((j >> 1) & 1) * 8;
        int c = c0 + (j & 1) + (j >> 2) * 8;
        v[j] = (c < NBRF) ? nbr_fea[(size_t)r*NBRF + c] : 0.f;
    }
    __half2 h0 = __floats2half2_rn(v[0], v[1]);
    __half2 h1 = __floats2half2_rn(v[2], v[3]);
    __half2 h2 = __floats2half2_rn(v[4], v[5]);
    __half2 h3 = __floats2half2_rn(v[6], v[7]);
    uint4 st;
    st.x = *(unsigned*)&h0; st.y = *(unsigned*)&h1;
    st.z = *(unsigned*)&h2; st.w = *(unsigned*)&h3;
    d_Ah[idx] = st;
}

// ---------------- layer-0: x -> A-fragment buffer ----------------
__global__ __launch_bounds__(256) void k_cvt_x()
{
    int idx  = blockIdx.x*256 + threadIdx.x;   // < (NATOMS/16)*4*32
    int lane = idx & 31;
    int ks   = (idx >> 5) & 3;
    int t    = idx >> 7;
    int r0 = t*16 + (lane >> 2);
    int c0 = ks*16 + (lane & 3)*2;

    float v[8];
    #pragma unroll
    for (int j = 0; j < 8; j++) {
        int r = r0 + ((j >> 1) & 1) * 8;
        int c = c0 + (j & 1) + (j >> 2) * 8;
        v[j] = d_x[r*AF + c];
    }
    __half2 h0 = __floats2half2_rn(v[0], v[1]);
    __half2 h1 = __floats2half2_rn(v[2], v[3]);
    __half2 h2 = __floats2half2_rn(v[4], v[5]);
    __half2 h3 = __floats2half2_rn(v[6], v[7]);
    uint4 st;
    st.x = *(unsigned*)&h0; st.y = *(unsigned*)&h1;
    st.z = *(unsigned*)&h2; st.w = *(unsigned*)&h3;
    d_Axh[idx] = st;
}

// ---------------- per-layer prep: zero stats + W converts (fused) ----------------
__global__ __launch_bounds__(256) void k_prep(const float* __restrict__ Wc)
{
    int idx = blockIdx.x*256 + threadIdx.x;   // grid covers 6144 + 4096
    if (idx < TWOAF) { d_s1[idx] = 0.f; d_q1[idx] = 0.f; }
    if (idx < AF)    { d_s2[idx] = 0.f; d_q2[idx] = 0.f; }

    if (idx < KPAD*TWOAF) {
        int k = idx >> 7, n = idx & 127;
        d_Weh[idx] = __float2half((k < NBRF) ? Wc[(size_t)(TWOAF + k)*TWOAF + n] : 0.f);
    } else {
        int widx = idx - KPAD*TWOAF;
        if (widx < 4096) {
            int lane = widx & 31;
            int ks   = (widx >> 5) & 3;
            int nt   = widx >> 7;
            int n  = nt*8 + (lane >> 2);
            int k0 = ks*16 + (lane & 3)*2;
            float w00, w01, w10, w11;
            if (n < TWOAF) {
                w00 = Wc[(k0    )*TWOAF + n]; w01 = Wc[(k0 + 1)*TWOAF + n];
                w10 = Wc[(k0 + 8)*TWOAF + n]; w11 = Wc[(k0 + 9)*TWOAF + n];
            } else {
                int nn = n - TWOAF;
                w00 = Wc[(AF + k0    )*TWOAF + nn]; w01 = Wc[(AF + k0 + 1)*TWOAF + nn];
                w10 = Wc[(AF + k0 + 8)*TWOAF + nn]; w11 = Wc[(AF + k0 + 9)*TWOAF + nn];
            }
            __half2 b0 = __floats2half2_rn(w00, w01);
            __half2 b1 = __floats2half2_rn(w10, w11);
            uint2 st;
            st.x = *(unsigned*)&b0; st.y = *(unsigned*)&b1;
            d_Wph[widx] = st;
        }
    }
}

// ---------------- atom GEMM via HMMA: P_self / P_nbr ----------------
__global__ __launch_bounds__(256) void k_atom_mma(const float* __restrict__ bc)
{
    int tid  = threadIdx.x;
    int warp = tid >> 5;
    int lane = tid & 31;
    int atile = blockIdx.x;

    float acc[4][4];
    #pragma unroll
    for (int nt = 0; nt < 4; nt++)
        #pragma unroll
        for (int j = 0; j < 4; j++) acc[nt][j] = 0.f;

    #pragma unroll
    for (int ks = 0; ks < 4; ks++) {
        uint4 a = d_Axh[(atile*4 + ks)*32 + lane];
        #pragma unroll
        for (int nt = 0; nt < 4; nt++) {
            uint2 b = d_Wph[((warp*4 + nt)*4 + ks)*32 + lane];
            asm volatile(
                "mma.sync.aligned.m16n8k16.row.col.f32.f16.f16.f32 "
                "{%0,%1,%2,%3}, {%4,%5,%6,%7}, {%8,%9}, {%0,%1,%2,%3};\n"
                : "+f"(acc[nt][0]), "+f"(acc[nt][1]), "+f"(acc[nt][2]), "+f"(acc[nt][3])
                : "r"(a.x), "r"(a.y), "r"(a.z), "r"(a.w), "r"(b.x), "r"(b.y));
        }
    }

    int r  = lane >> 2;
    int a0 = atile * 16;
    bool self = (warp < 4);
    __half* dst = self ? d_Psh : d_Pnh;
    #pragma unroll
    for (int nt = 0; nt < 4; nt++) {
        int c = warp*32 + nt*8 + (lane & 3)*2;
        float b0 = 0.f, b1 = 0.f;
        if (self) { b0 = bc[c]; b1 = bc[c + 1]; }
        int cc = self ? c : c - TWOAF;
        __half2 h0 = __floats2half2_rn(acc[nt][0] + b0, acc[nt][1] + b1);
        __half2 h1 = __floats2half2_rn(acc[nt][2] + b0, acc[nt][3] + b1);
        *(__half2*)&dst[(size_t)(a0 + r    )*TWOAF + cc] = h0;
        *(__half2*)&dst[(size_t)(a0 + r + 8)*TWOAF + cc] = h1;
    }
}

// ---------------- edge kernel: HMMA GEMM + STSM accumulator store + gather epilogue + BN1 stats ----------------
// persistent; block tile = 64 edges x 128 cols; warp w covers cols w*16..+15
__global__ __launch_bounds__(256, 2) void k_edge_mma(
    const int* __restrict__ nbr_idx)
{
    __shared__ __half C_sh[64*136];
    __shared__ int nb_sh[64];

    int tid  = threadIdx.x;
    int warp = tid >> 5;
    int lane = tid & 31;
    int eg   = tid & 15;
    int cg   = tid >> 4;

    unsigned bfrag[2][3][2];
    {
        int nb_ = warp*16 + (lane >> 2);
        #pragma unroll
        for (int nt = 0; nt < 2; nt++) {
            int n = nb_ + nt*8;
            #pragma unroll
            for (int ks = 0; ks < 3; ks++) {
                int k0 = ks*16 + (lane & 3)*2;
                __half2 b0 = __halves2half2(d_Weh[k0*TWOAF + n],     d_Weh[(k0+1)*TWOAF + n]);
                __half2 b1 = __halves2half2(d_Weh[(k0+8)*TWOAF + n], d_Weh[(k0+9)*TWOAF + n]);
                bfrag[nt][ks][0] = *(unsigned*)&b0;
                bfrag[nt][ks][1] = *(unsigned*)&b1;
            }
        }
    }

    float s8[8], q8[8];
    #pragma unroll
    for (int j = 0; j < 8; j++) { s8[j] = 0.f; q8[j] = 0.f; }

    // stmatrix address: quadrant selection by lane group
    // lanes 0-7: (row+0,col+0); 8-15: (row+8,col+0); 16-23: (row+0,col+8); 24-31: (row+8,col+8)
    unsigned c_smem_base = (unsigned)__cvta_generic_to_shared(C_sh);
    int row_sel = (lane & 7) + ((lane >> 3) & 1) * 8;
    int col_sel = warp*16 + ((lane >> 4) & 1) * 8;
    unsigned stm_base = c_smem_base + (unsigned)((row_sel*136 + col_sel) * 2);

    for (int tile = blockIdx.x; tile < NT64; tile += gridDim.x) {
        __syncthreads();
        if (tid < 16) *(int4*)&nb_sh[tid*4] = *(const int4*)&nbr_idx[tile*64 + tid*4];

        float acc[4][2][4];
        #pragma unroll
        for (int mt = 0; mt < 4; mt++)
            #pragma unroll
            for (int nt = 0; nt < 2; nt++)
                #pragma unroll
                for (int j = 0; j < 4; j++) acc[mt][nt][j] = 0.f;

        #pragma unroll
        for (int ks = 0; ks < 3; ks++) {
            #pragma unroll
            for (int mt = 0; mt < 4; mt++) {
                uint4 a = d_Ah[(size_t)((tile*4 + mt)*3 + ks)*32 + lane];
                #pragma unroll
                for (int nt = 0; nt < 2; nt++) {
                    asm volatile(
                        "mma.sync.aligned.m16n8k16.row.col.f32.f16.f16.f32 "
                        "{%0,%1,%2,%3}, {%4,%5,%6,%7}, {%8,%9}, {%0,%1,%2,%3};\n"
                        : "+f"(acc[mt][nt][0]), "+f"(acc[mt][nt][1]),
                          "+f"(acc[mt][nt][2]), "+f"(acc[mt][nt][3])
                        : "r"(a.x), "r"(a.y), "r"(a.z), "r"(a.w),
                          "r"(bfrag[nt][ks][0]), "r"(bfrag[nt][ks][1]));
                }
            }
        }

        // store accumulators to C_sh: one stmatrix.x4 per mt (replaces 4x STS.32 pairs)
        #pragma unroll
        for (int mt = 0; mt < 4; mt++) {
            __half2 a0 = __floats2half2_rn(acc[mt][0][0], acc[mt][0][1]);  // (r, c) nt0
            __half2 a1 = __floats2half2_rn(acc[mt][0][2], acc[mt][0][3]);  // (r+8, c) nt0
            __half2 a2 = __floats2half2_rn(acc[mt][1][0], acc[mt][1][1]);  // (r, c) nt1
            __half2 a3 = __floats2half2_rn(acc[mt][1][2], acc[mt][1][3]);  // (r+8, c) nt1
            unsigned addr = stm_base + (unsigned)(mt * 16 * 136 * 2);
            asm volatile(
                "stmatrix.sync.aligned.m8n8.x4.shared.b16 [%0], {%1,%2,%3,%4};\n"
                :: "r"(addr),
                   "r"(*(unsigned*)&a0), "r"(*(unsigned*)&a1),
                   "r"(*(unsigned*)&a2), "r"(*(unsigned*)&a3)
                : "memory");
        }
        __syncthreads();

        #pragma unroll
        for (int i = 0; i < 4; i++) {
            int el = eg + 16*i;
            int e  = tile*64 + el;
            int a_ = e / MNBR;
            int nb = nb_sh[el];
            uint4 cvv = *(const uint4*)&C_sh[el*136 + cg*8];
            uint4 psv = *reinterpret_cast<const uint4*>(&d_Psh[(size_t)a_*TWOAF + cg*8]);
            uint4 pnv = *reinterpret_cast<const uint4*>(&d_Pnh[(size_t)nb*TWOAF + cg*8]);
            const __half2* ch = (const __half2*)&cvv;
            const __half2* ph = (const __half2*)&psv;
            const __half2* nh = (const __half2*)&pnv;
            float g[8];
            #pragma unroll
            for (int p = 0; p < 4; p++) {
                float2 cf = __half22float2(ch[p]);
                float2 pf = __half22float2(ph[p]);
                float2 nf = __half22float2(nh[p]);
                g[2*p]   = cf.x + pf.x + nf.x;
                g[2*p+1] = cf.y + pf.y + nf.y;
            }
            #pragma unroll
            for (int j = 0; j < 8; j++) { s8[j] += g[j]; q8[j] += g[j]*g[j]; }
            __half2 h[4];
            #pragma unroll
            for (int p = 0; p < 4; p++) h[p] = __floats2half2_rn(g[2*p], g[2*p+1]);
            uint4 st;
            st.x = *(unsigned*)&h[0]; st.y = *(unsigned*)&h[1];
            st.z = *(unsigned*)&h[2]; st.w = *(unsigned*)&h[3];
            *reinterpret_cast<uint4*>(&d_gh[(size_t)e*TWOAF + cg*8]) = st;
        }
    }

    #pragma unroll
    for (int m = 1; m < 16; m <<= 1) {
        #pragma unroll
        for (int j = 0; j < 8; j++) {
            s8[j] += __shfl_xor_sync(0xffffffffu, s8[j], m);
            q8[j] += __shfl_xor_sync(0xffffffffu, q8[j], m);
        }
    }
    if (eg == 0) {
        #pragma unroll
        for (int j = 0; j < 8; j++) {
            atomicAdd(&d_s1[cg*8 + j], s8[j]);
            atomicAdd(&d_q1[cg*8 + j], q8[j]);
        }
    }
}

// ---------------- gate + sum (fp16 input), BN1 finalize inlined, BN2 stats ----------------
// block = 32 atoms x 8 threads; thread covers 8 cols
__global__ __launch_bounds__(256) void k_gate_sum(
    const float* __restrict__ g1, const float* __restrict__ b1)
{
    __shared__ float sc1[TWOAF], sh1[TWOAF];
    __shared__ float s2_sh[AF], q2_sh[AF];
    int tid = threadIdx.x;
    if (tid < TWOAF) {
        float inv_n = 1.0f / (float)EDGES;
        float mu  = d_s1[tid] * inv_n;
        float var = d_q1[tid] * inv_n - mu*mu;
        float sc  = rsqrtf(var + BNEPS) * g1[tid];
        sc1[tid] = sc;
        sh1[tid] = b1[tid] - mu * sc;
    }
    if (tid < AF) { s2_sh[tid] = 0.f; q2_sh[tid] = 0.f; }
    __syncthreads();

    int al = tid >> 3;
    int c0 = (tid & 7) * 8;
    int a  = blockIdx.x*32 + al;

    float scf[8], shf[8], scs[8], shs[8];
    #pragma unroll
    for (int j = 0; j < 8; j++) {
        scf[j] = sc1[c0 + j];      shf[j] = sh1[c0 + j];
        scs[j] = sc1[AF + c0 + j]; shs[j] = sh1[AF + c0 + j];
    }

    float accv[8];
    #pragma unroll
    for (int j = 0; j < 8; j++) accv[j] = 0.f;

    size_t base = (size_t)a * MNBR * TWOAF;
    #pragma unroll
    for (int m = 0; m < MNBR; m++) {
        uint4 fv = *reinterpret_cast<const uint4*>(&d_gh[base + m*TWOAF + c0]);
        uint4 sv = *reinterpret_cast<const uint4*>(&d_gh[base + m*TWOAF + AF + c0]);
        const __half2* fh = (const __half2*)&fv;
        const __half2* sh = (const __half2*)&sv;
        #pragma unroll
        for (int p = 0; p < 4; p++) {
            float2 f = __half22float2(fh[p]);
            float2 s = __half22float2(sh[p]);
            float fx = f.x*scf[2*p]   + shf[2*p];
            float fy = f.y*scf[2*p+1] + shf[2*p+1];
            float sx = s.x*scs[2*p]   + shs[2*p];
            float sy = s.y*scs[2*p+1] + shs[2*p+1];
            accv[2*p]   += sigmoidf(fx) * softplusf(sx);
            accv[2*p+1] += sigmoidf(fy) * softplusf(sy);
        }
    }
    *(float4*)&d_summed[a*AF + c0]     = *(float4*)&accv[0];
    *(float4*)&d_summed[a*AF + c0 + 4] = *(float4*)&accv[4];
    #pragma unroll
    for (int j = 0; j < 8; j++) {
        atomicAdd(&s2_sh[c0 + j], accv[j]);
        atomicAdd(&q2_sh[c0 + j], accv[j]*accv[j]);
    }
    __syncthreads();
    if (tid < AF) {
        atomicAdd(&d_s2[tid], s2_sh[tid]);
        atomicAdd(&d_q2[tid], q2_sh[tid]);
    }
}

// ---------------- fused: BN2 finalize + x update + A-fragment emission ----------------
// block = 16 atoms (grid 2048)
__global__ __launch_bounds__(256) void k_update_cvt(
    const float* __restrict__ g2, const float* __restrict__ b2)
{
    __shared__ float x_sh[16*64];
    __shared__ float sc2[AF], sh2[AF];
    int tid  = threadIdx.x;
    if (tid < AF) {
        float inv_n = 1.0f / (float)NATOMS;
        float mu  = d_s2[tid] * inv_n;
        float var = d_q2[tid] * inv_n - mu*mu;
        float sc  = rsqrtf(var + BNEPS) * g2[tid];
        sc2[tid] = sc;
        sh2[tid] = b2[tid] - mu * sc;
    }
    __syncthreads();

    int base = blockIdx.x*1024 + tid*4;
    int c    = (tid*4) & 63;

    float4 sm = *(const float4*)&d_summed[base];
    float4 xv = *(const float4*)&d_x[base];
    float4 nx;
    nx.x = softplusf(xv.x + sm.x*sc2[c]   + sh2[c]);
    nx.y = softplusf(xv.y + sm.y*sc2[c+1] + sh2[c+1]);
    nx.z = softplusf(xv.z + sm.z*sc2[c+2] + sh2[c+2]);
    nx.w = softplusf(xv.w + sm.w*sc2[c+3] + sh2[c+3]);
    *(float4*)&d_x[base]   = nx;
    *(float4*)&x_sh[tid*4] = nx;
    __syncthreads();

    if (tid < 128) {
        int ks = tid >> 5, lane = tid & 31;
        int r0 = lane >> 2;
        int c0 = ks*16 + (lane & 3)*2;
        float v[8];
        #pragma unroll
        for (int j = 0; j < 8; j++) {
            int r  = r0 + ((j >> 1) & 1) * 8;
            int cc = c0 + (j & 1) + (j >> 2) * 8;
            v[j] = x_sh[r*64 + cc];
        }
        __half2 h0 = __floats2half2_rn(v[0], v[1]);
        __half2 h1 = __floats2half2_rn(v[2], v[3]);
        __half2 h2 = __floats2half2_rn(v[4], v[5]);
        __half2 h3 = __floats2half2_rn(v[6], v[7]);
        uint4 st;
        st.x = *(unsigned*)&h0; st.y = *(unsigned*)&h1;
        st.z = *(unsigned*)&h2; st.w = *(unsigned*)&h3;
        d_Axh[(blockIdx.x*4 + ks)*32 + lane] = st;
    }
}

// ---------------- pool + head MLP ----------------
__global__ __launch_bounds__(128) void k_head(
    const float* __restrict__ fc1W, const float* __restrict__ fc1b,
    const float* __restrict__ fc2W, const float* __restrict__ fc2b,
    const float* __restrict__ outW, const float* __restrict__ outb,
    float* __restrict__ out)
{
    __shared__ float p[AF];
    __shared__ float h1[HF];
    __shared__ float red[HF];
    int tid = threadIdx.x;
    int b = blockIdx.x;

    if (tid < AF) {
        const float* xb = &d_x[(size_t)b * ATOMS_PER * AF];
        float s = 0.f;
        #pragma unroll
        for (int a = 0; a < ATOMS_PER; a++) s += xb[a*AF + tid];
        p[tid] = softplusf(s * (1.0f/ATOMS_PER));
    }
    __syncthreads();

    float acc = fc1b[tid];
    #pragma unroll 4
    for (int k = 0; k < AF; k++) acc += p[k] * fc1W[k*HF + tid];
    h1[tid] = softplusf(acc);
    __syncthreads();

    float acc2 = fc2b[tid];
    #pragma unroll 4
    for (int k = 0; k < HF; k++) acc2 += h1[k] * fc2W[k*HF + tid];
    float h2 = softplusf(acc2);

    red[tid] = h2 * outW[tid];
    __syncthreads();
    for (int s = HF/2; s > 0; s >>= 1) {
        if (tid < s) red[tid] += red[tid + s];
        __syncthreads();
    }
    if (tid == 0) out[b] = red[0] + outb[0];
}

// ---------------- launch ----------------
extern "C" void kernel_launch(void* const* d_in, const int* in_sizes, int n_in,
                              void* d_out, int out_size)
{
    const float* atom_fea = (const float*)d_in[0];
    const float* nbr_fea  = (const float*)d_in[1];
    const int*   nbr_idx  = (const int*)  d_in[2];
    const float* embW  = (const float*)d_in[4];
    const float* embB  = (const float*)d_in[5];
    const float* convW = (const float*)d_in[6];
    const float* convB = (const float*)d_in[7];
    const float* bn1g  = (const float*)d_in[8];
    const float* bn1b  = (const float*)d_in[9];
    const float* bn2g  = (const float*)d_in[10];
    const float* bn2b  = (const float*)d_in[11];
    const float* fc1W  = (const float*)d_in[12];
    const float* fc1b  = (const float*)d_in[13];
    const float* fc2W  = (const float*)d_in[14];
    const float* fc2b  = (const float*)d_in[15];
    const float* outW  = (const float*)d_in[16];
    const float* outb  = (const float*)d_in[17];
    float* out = (float*)d_out;

    k_embed<<<NATOMS/4, 256>>>(atom_fea, embW, embB);
    k_cvt_nbr<<<(EDGES/16)*3*32/256, 256>>>(nbr_fea);   // once: layer-invariant
    k_cvt_x<<<(NATOMS/16)*4*32/256, 256>>>();           // layer-0 fragments

    for (int l = 0; l < NCONV; l++) {
        const float* Wl = convW + (size_t)l*KTOT*TWOAF;
        k_prep<<<(KPAD*TWOAF + 4096 + 255)/256, 256>>>(Wl);
        k_atom_mma<<<NATOMS/16, 256>>>(convB + l*TWOAF);
        k_edge_mma<<<296, 256>>>(nbr_idx);
        k_gate_sum<<<NATOMS/32, 256>>>(bn1g + l*TWOAF, bn1b + l*TWOAF);
        k_update_cvt<<<NATOMS*AF/1024, 256>>>(bn2g + l*AF, bn2b + l*AF);
    }

    k_head<<<NCRYS, 128>>>(fc1W, fc1b, fc2W, fc2b, outW, outb, out);
}